// round 16
// baseline (speedup 1.0000x reference)
#include <cuda_runtime.h>
#include <math.h>

// DDSL spec: B=2, NV=NE=512, RES=(128,128) -> freq grid 128 x 65, J=2.
// EDGE-PAIR packed kernel: f32x2 packs TWO CONSECUTIVE RING EDGES (same
// frequency), so per-freq phase state stays scalar (no packed-state register
// blowup). Warp = one (freq, batch); lane = 16 edges as two independent
// chains of 4 pair-steps. Per pair-step: 2 vertex sincos + ONE shared rcp
// for both edges (pd = d0*d1, sanitized). Ring reuse: vert v2 of pair m is
// v0 of pair m+1.

#define NV      512
#define NE      512
#define FX      128
#define FY2     65
#define NF      (FX * FY2)          // 8320 freqs
#define BLOCK   256

typedef unsigned long long u64;

__device__ __forceinline__ u64 pk2(float a, float b) {
    u64 r; asm("mov.b64 %0, {%1, %2};" : "=l"(r) : "f"(a), "f"(b)); return r;
}
__device__ __forceinline__ void upk(u64 v, float& a, float& b) {
    asm("mov.b64 {%0, %1}, %2;" : "=f"(a), "=f"(b) : "l"(v));
}
__device__ __forceinline__ u64 f2fma(u64 a, u64 b, u64 c) {
    u64 d; asm("fma.rn.f32x2 %0, %1, %2, %3;" : "=l"(d) : "l"(a), "l"(b), "l"(c)); return d;
}
__device__ __forceinline__ u64 f2add(u64 a, u64 b) {
    u64 d; asm("add.rn.f32x2 %0, %1, %2;" : "=l"(d) : "l"(a), "l"(b)); return d;
}
__device__ __forceinline__ u64 f2mul(u64 a, u64 b) {
    u64 d; asm("mul.rn.f32x2 %0, %1, %2;" : "=l"(d) : "l"(a), "l"(b)); return d;
}

__device__ __forceinline__ float fracr(float t) {
    const float MAGIC = 12582912.0f;  // 1.5 * 2^23
    float g = __fadd_rn(t, MAGIC);
    float r = __fadd_rn(g, -MAGIC);
    return t - r;
}

__global__ __launch_bounds__(BLOCK, 4)
void ddsl_spec_kernel(const float* __restrict__ V,
                      const int*   __restrict__ E,
                      const float* __restrict__ D,
                      float*       __restrict__ out)
{
    // stride-33 padded layout: idx(e) = e + (e>>5); proven conflict-free.
    __shared__ float sX[529];
    __shared__ float sY[529];
    __shared__ float sCD[528];

    const int b = blockIdx.y;

    // ---- stage ring vertices + C*D ----
    for (int e = threadIdx.x; e < NE; e += BLOCK) {
        int i0 = E[(b * NE + e) * 2 + 0];
        int i1 = E[(b * NE + e) * 2 + 1];
        float ax = V[(b * NV + i0) * 2 + 0];
        float ay = V[(b * NV + i0) * 2 + 1];
        float bx = V[(b * NV + i1) * 2 + 0];
        float by = V[(b * NV + i1) * 2 + 1];
        int p = e + (e >> 5);
        sX[p] = ax;
        sY[p] = ay;
        sCD[p] = (ax * by - ay * bx) * D[b * NE + e];
        if (e == 0) { sX[528] = ax; sY[528] = ay; }   // vertex 512 = vertex 0
    }
    __syncthreads();

    const int lane = threadIdx.x & 31;
    const int fp   = blockIdx.x * 8 + (threadIdx.x >> 5);   // freq index

    const int fx = fp / FY2;
    const int fy = fp - fx * FY2;
    const int kx = (fx < FX / 2) ? fx : fx - FX;
    const float fkx = (float)kx;
    const float fky = (float)fy;

    const float TWO_PI = 6.28318530717958647692f;
    const u64 NEG1 = pk2(-1.0f, -1.0f);

    // lane's 16-edge chunk: pad(16*lane + j) = base + j for j <= 15;
    // vertex 16 of the chunk sits at base + 16 + (lane & 1).
    const int base = 16 * lane + (lane >> 1);
    const float* xb = &sX[base];
    const float* yb = &sY[base];
    const float* cb = &sCD[base];
    const int lastoff = 16 + (lane & 1);

    // scalar vertex phase at shared offset OFS (sin first, cos second)
#define VERT(OFS, T, C, S)                                                 \
    {                                                                      \
        float vx = xb[OFS], vy = yb[OFS];                                  \
        T = fmaf(vy, fky, vx * fkx);                                       \
        __sincosf(fracr(T) * TWO_PI, &S, &C);                              \
    }

    // pair-step: edges (v0=state, v1) and (v1, v2); packed over the 2 edges
#define PSTEP(TP, CP, SP, O1, O2, CO0, CO1, AR, AI)                        \
    {                                                                      \
        float t1, c1, s1, t2, c2, s2;                                      \
        VERT(O1, t1, c1, s1);                                              \
        VERT(O2, t2, c2, s2);                                              \
        u64 Ta = pk2(TP, t1), Tb = pk2(t1, t2);                            \
        u64 Ca = pk2(CP, c1), Cb = pk2(c1, c2);                            \
        u64 Sa = pk2(SP, s1), Sb = pk2(s1, s2);                            \
        u64 dt  = f2fma(Tb, NEG1, Ta);                                     \
        u64 den = f2mul(f2mul(Ta, Tb), dt);                                \
        u64 nta = f2mul(Ta, NEG1);                                         \
        u64 nr  = f2fma(Cb, nta, f2fma(Ca, Tb, dt));                       \
        u64 ni  = f2fma(Sb, nta, f2mul(Sa, Tb));                           \
        float d0, d1; upk(den, d0, d1);                                    \
        float cd0 = cb[CO0], cd1 = cb[CO1];                                \
        float pd = d0 * d1;                                                \
        pd = (pd == 0.0f) ? 1.0f : pd;                                     \
        float rp = __fdividef(1.0f, pd);                                   \
        u64 rc = pk2(cd0 * rp * d1, cd1 * rp * d0);                        \
        AR = f2fma(nr, rc, AR);                                            \
        AI = f2fma(ni, rc, AI);                                            \
        TP = t2; CP = c2; SP = s2;                                         \
    }

    u64 aR0 = pk2(0.0f, 0.0f), aI0 = pk2(0.0f, 0.0f);
    u64 aR1 = pk2(0.0f, 0.0f), aI1 = pk2(0.0f, 0.0f);

    float tA, cA, sA, tB, cB, sB;
    VERT(0, tA, cA, sA);      // chain A: edges 0..7  (verts 0..8)
    VERT(8, tB, cB, sB);      // chain B: edges 8..15 (verts 8..16/wrap)

#pragma unroll
    for (int m = 0; m < 4; ++m) {
        PSTEP(tA, cA, sA, 2 * m + 1, 2 * m + 2, 2 * m, 2 * m + 1, aR0, aI0);
        const int o2b = (m == 3) ? lastoff : 2 * m + 10;
        PSTEP(tB, cB, sB, 2 * m + 9, o2b, 2 * m + 8, 2 * m + 9, aR1, aI1);
    }

    u64 accR = f2add(aR0, aR1);
    u64 accI = f2add(aI0, aI1);   // holds -Im (both halves same freq)

    // ---- reduce the 32 lanes (packed) ----
#pragma unroll
    for (int off = 16; off > 0; off >>= 1) {
        accR = f2add(accR, __shfl_down_sync(0xFFFFFFFFu, accR, off));
        accI = f2add(accI, __shfl_down_sync(0xFFFFFFFFu, accI, off));
    }

    if (lane == 0) {
        // fold lo+hi (two edge-halves of the SAME freq), then scale.
        const float SCALE = (float)(-16384.0 / (4.0 * 3.14159265358979323846
                                                    * 3.14159265358979323846));
        float Rl, Rh, Il, Ih;
        upk(accR, Rl, Rh);
        upk(accI, Il, Ih);
        float oR =  SCALE * (Rl + Rh);
        float oI = -SCALE * (Il + Ih);

        if (fp == 0) {
            // DC: F[:,0,0,:,:] = 8192*sum(C*D) in BOTH re and im
            float s = 0.0f;
#pragma unroll 8
            for (int e = 0; e < NE; ++e) s += sCD[e + (e >> 5)];
            oR = 8192.0f * s;
            oI = oR;
        }

        int obase = ((b * FX + fx) * FY2 + fy) * 2;
        out[obase + 0] = oR;
        out[obase + 1] = oI;
    }
}

extern "C" void kernel_launch(void* const* d_in, const int* in_sizes, int n_in,
                              void* d_out, int out_size)
{
    const float* V = (const float*)d_in[0];
    const int*   E = (const int*)  d_in[1];
    const float* D = (const float*)d_in[2];
    float* out = (float*)d_out;

    const int B = in_sizes[0] / (NV * 2);   // 2
    dim3 grid(NF / 8, B);                   // (1040, 2) = 2080 blocks
    ddsl_spec_kernel<<<grid, BLOCK>>>(V, E, D, out);
}

// round 17
// speedup vs baseline: 1.1555x; 1.1555x over previous
#include <cuda_runtime.h>
#include <math.h>

// DDSL spec: B=2, NV=NE=512, RES=(128,128) -> freq grid 128 x 65, J=2.
// Direct packed kernel: two adjacent fx freqs (kx,kx+1) per thread (f32x2).
// One warp per freq-pair; each lane's 16 edges split into THREE independent
// ring chains (6+5+5) for 3-way ILP, accumulating into SHARED packed
// accumulators. Ring reuse: 1 vertex sincos per edge. Single product-rcp
// divide with dlo sanitize (junk only in DC slot, overwritten).

#define NV      512
#define NE      512
#define FX      128
#define FY2     65
#define NFP     (FX / 2 * FY2)      // 4160 fx-pairs
#define GROUPS  8                   // freq-pairs (warps) per block
#define BLOCK   256
#define PADDED  529                 // pad(e)=e+(e>>5); pad(512)=528 wrap dup

typedef unsigned long long u64;

__device__ __forceinline__ u64 pk2(float a, float b) {
    u64 r; asm("mov.b64 %0, {%1, %2};" : "=l"(r) : "f"(a), "f"(b)); return r;
}
__device__ __forceinline__ void upk(u64 v, float& a, float& b) {
    asm("mov.b64 {%0, %1}, %2;" : "=f"(a), "=f"(b) : "l"(v));
}
__device__ __forceinline__ u64 f2fma(u64 a, u64 b, u64 c) {
    u64 d; asm("fma.rn.f32x2 %0, %1, %2, %3;" : "=l"(d) : "l"(a), "l"(b), "l"(c)); return d;
}
__device__ __forceinline__ u64 f2add(u64 a, u64 b) {
    u64 d; asm("add.rn.f32x2 %0, %1, %2;" : "=l"(d) : "l"(a), "l"(b)); return d;
}
__device__ __forceinline__ u64 f2mul(u64 a, u64 b) {
    u64 d; asm("mul.rn.f32x2 %0, %1, %2;" : "=l"(d) : "l"(a), "l"(b)); return d;
}

__device__ __forceinline__ float fracr(float t) {
    const float MAGIC = 12582912.0f;  // 1.5 * 2^23
    float g = __fadd_rn(t, MAGIC);
    float r = __fadd_rn(g, -MAGIC);
    return t - r;
}

__global__ __launch_bounds__(BLOCK, 4)
void ddsl_spec_kernel(const float* __restrict__ V,
                      const int*   __restrict__ E,
                      const float* __restrict__ D,
                      float*       __restrict__ out)
{
    __shared__ float sX[PADDED];
    __shared__ float sY[PADDED];
    __shared__ float sCD[PADDED];

    const int b = blockIdx.y;

    // ---- stage ring vertices + C*D ----
    for (int e = threadIdx.x; e < NE; e += BLOCK) {
        int i0 = E[(b * NE + e) * 2 + 0];
        int i1 = E[(b * NE + e) * 2 + 1];
        float ax = V[(b * NV + i0) * 2 + 0];
        float ay = V[(b * NV + i0) * 2 + 1];
        float bx = V[(b * NV + i1) * 2 + 0];
        float by = V[(b * NV + i1) * 2 + 1];
        int p = e + (e >> 5);
        sX[p] = ax;
        sY[p] = ay;
        sCD[p] = (ax * by - ay * bx) * D[b * NE + e];
        if (e == 0) { sX[528] = ax; sY[528] = ay; }   // ring wrap dup
    }
    __syncthreads();

    const int lane = threadIdx.x & 31;
    const int fp   = blockIdx.x * GROUPS + (threadIdx.x >> 5);

    const int fxp = fp / FY2;
    const int fy  = fp - fxp * FY2;
    const int fx0 = 2 * fxp;
    const int kx0 = (fx0 < FX / 2) ? fx0 : fx0 - FX;   // kx1 = kx0 + 1
    const float fkx = (float)kx0;
    const float fky = (float)fy;

    const float TWO_PI = 6.28318530717958647692f;
    const float MAGIC  = 12582912.0f;
    const u64 MAGIC2 = pk2(MAGIC, MAGIC);
    const u64 NEG1   = pk2(-1.0f, -1.0f);
    const u64 TWOPI2 = pk2(TWO_PI, TWO_PI);

    // lane's 16-edge chunk: pad(16*lane + j) = 16*lane + (lane>>1) + j,
    // j = 0..15; final ring vertex at offset 16 + (lane & 1).
    const int base = 16 * lane + (lane >> 1);
    const float* xb = &sX[base];
    const float* yb = &sY[base];
    const float* cb = &sCD[base];
    const int lastoff = 16 + (lane & 1);

#define INITV(OFS, T, C, S)                                                \
    {                                                                      \
        float vx = xb[OFS], vy = yb[OFS];                                  \
        float tl = fmaf(vy, fky, vx * fkx);                                \
        float th = tl + vx;                                                \
        float sl, cl, sh, chh;                                             \
        __sincosf(fracr(tl) * TWO_PI, &sl, &cl);                           \
        __sincosf(fracr(th) * TWO_PI, &sh, &chh);                          \
        T = pk2(tl, th); C = pk2(cl, chh); S = pk2(sl, sh);                \
    }

#define STEP(T, C, S, OFS, CDOFS)                                          \
    {                                                                      \
        float nx = xb[OFS], ny = yb[OFS];                                  \
        float cd = cb[CDOFS];                                              \
        float t1lo = fmaf(ny, fky, nx * fkx);                              \
        u64 T1 = pk2(t1lo, t1lo + nx);                                     \
        u64 g  = f2add(T1, MAGIC2);                                        \
        u64 rr = f2fma(MAGIC2, NEG1, g);                                   \
        u64 uu = f2fma(rr, NEG1, T1);                                      \
        u64 ph = f2mul(uu, TWOPI2);                                        \
        float plo, phi_, sl, cl, sh, chh;                                  \
        upk(ph, plo, phi_);                                                \
        __sincosf(plo, &sl, &cl);                                          \
        __sincosf(phi_, &sh, &chh);                                        \
        u64 SN1 = pk2(sl, sh), CS1 = pk2(cl, chh);                         \
        u64 dt  = f2fma(T1, NEG1, T);                                      \
        u64 den = f2mul(f2mul(T, T1), dt);                                 \
        u64 nt  = f2mul(T, NEG1);                                          \
        u64 nr  = f2fma(CS1, nt, f2fma(C, T1, dt));                        \
        u64 ni  = f2fma(SN1, nt, f2mul(S, T1));                            \
        float dlo, dhi; upk(den, dlo, dhi);                                \
        dlo = (dlo == 0.0f) ? 1.0f : dlo;                                  \
        float rp = __fdividef(cd, dlo * dhi);                              \
        u64 rc = pk2(rp * dhi, rp * dlo);                                  \
        accR = f2fma(nr, rc, accR);                                        \
        accI = f2fma(ni, rc, accI);                                        \
        T = T1; C = CS1; S = SN1;                                          \
    }

    u64 accR = pk2(0.0f, 0.0f);
    u64 accI = pk2(0.0f, 0.0f);   // accumulates -Im

    u64 TA, CA, SA, TB, CB, SB, TC, CC, SC;
    INITV(0,  TA, CA, SA);     // chain A: edges 0..5   (verts 0..6)
    INITV(6,  TB, CB, SB);     // chain B: edges 6..10  (verts 6..11)
    INITV(11, TC, CC, SC);     // chain C: edges 11..15 (verts 11..16/wrap)

#pragma unroll
    for (int i = 0; i < 5; ++i) {
        STEP(TA, CA, SA, i + 1, i);                               // A: 5 of 6
        STEP(TB, CB, SB, 7 + i, 6 + i);                           // B: 5
        const int offC = (i == 4) ? lastoff : 12 + i;             // C: 5
        STEP(TC, CC, SC, offC, 11 + i);
    }
    STEP(TA, CA, SA, 6, 5);                                       // A: 6th

    // ---- reduce the 32 lanes (packed) ----
#pragma unroll
    for (int off = 16; off > 0; off >>= 1) {
        accR = f2add(accR, __shfl_down_sync(0xFFFFFFFFu, accR, off));
        accI = f2add(accI, __shfl_down_sync(0xFFFFFFFFu, accI, off));
    }

    if (lane == 0) {
        // F = -einsum * RES^J ; (2*pi)^-2 folded into SCALE. accI = -Im.
        const float SCALE = (float)(-16384.0 / (4.0 * 3.14159265358979323846
                                                    * 3.14159265358979323846));
        float aRlo, aRhi, aIlo, aIhi;
        upk(accR, aRlo, aRhi);
        upk(accI, aIlo, aIhi);
        float oRlo =  SCALE * aRlo, oRhi =  SCALE * aRhi;
        float oIlo = -SCALE * aIlo, oIhi = -SCALE * aIhi;

        if (fp == 0) {
            // DC: F[:,0,0,:,:] = 8192*sum(C*D) in BOTH re and im
            float s = 0.0f;
#pragma unroll 8
            for (int e = 0; e < NE; ++e) s += sCD[e + (e >> 5)];
            oRlo = 8192.0f * s;
            oIlo = oRlo;
        }

        int obase = ((b * FX + fx0) * FY2 + fy) * 2;
        out[obase + 0] = oRlo;
        out[obase + 1] = oIlo;
        out[obase + 2 * FY2 + 0] = oRhi;   // fx0 + 1
        out[obase + 2 * FY2 + 1] = oIhi;
    }
}

extern "C" void kernel_launch(void* const* d_in, const int* in_sizes, int n_in,
                              void* d_out, int out_size)
{
    const float* V = (const float*)d_in[0];
    const int*   E = (const int*)  d_in[1];
    const float* D = (const float*)d_in[2];
    float* out = (float*)d_out;

    const int B = in_sizes[0] / (NV * 2);   // 2
    dim3 grid(NFP / GROUPS, B);             // (520, 2) = 1040 blocks
    ddsl_spec_kernel<<<grid, BLOCK>>>(V, E, D, out);
}